// round 11
// baseline (speedup 1.0000x reference)
#include <cuda_runtime.h>
#include <cuda_fp16.h>
#include <cstdint>
#include <math.h>

// ---------------------------------------------------------------- constants
#define RR 8
#define NN 128
#define DD 512
#define HH 256
#define KTOP 64
#define NCAP 512               // candidate capacity
#define NPAIR (NN*NN)          // 16384
#define KC 64                  // K per chunk (64 fp16 = 128B rows, SW128 atom)
#define NCH 8                  // 512 / 64
#define STG 81920              // bytes per smem stage (A + B_hi + B_lo)
#define OFF_A   0              // 16384 B  (128 rows x 128B)
#define OFF_BHI 16384          // 32768 B  (256 rows x 128B)
#define OFF_BLO 49152          // 32768 B
#define SWZ(o) ((o) ^ (((o) >> 3) & 0x70))

// ---------------------------------------------------------------- scratch
__device__ float g_pf[KTOP * DD];                 // gathered mean pair feats
__device__ int   g_topk[KTOP];
__device__ int   g_cand[NCAP];
__device__ float g_cand_logit[NCAP];
__device__ int   g_ncand;
__device__ __align__(16) __half g_whi[2][NCH * 16384]; // W split hi (fp16)
__device__ __align__(16) __half g_wlo[2][NCH * 16384]; // W split lo (fp16)

// ---------------------------------------------------------------- helpers
static __device__ __forceinline__ uint32_t smem_u32(const void* p) {
    uint32_t a;
    asm("{ .reg .u64 t; cvta.to.shared.u64 t, %1; cvt.u32.u64 %0, t; }"
        : "=r"(a) : "l"(p));
    return a;
}
static __device__ __forceinline__ void ldsm4(uint32_t* r, uint32_t addr) {
    asm volatile("ldmatrix.sync.aligned.m8n8.x4.shared.b16 {%0,%1,%2,%3}, [%4];"
                 : "=r"(r[0]), "=r"(r[1]), "=r"(r[2]), "=r"(r[3]) : "r"(addr));
}
static __device__ __forceinline__ void mma16816(float* d, const uint32_t* a,
                                                uint32_t b0, uint32_t b1) {
    asm volatile(
        "mma.sync.aligned.m16n8k16.row.col.f32.f16.f16.f32 "
        "{%0,%1,%2,%3}, {%4,%5,%6,%7}, {%8,%9}, {%0,%1,%2,%3};"
        : "+f"(d[0]), "+f"(d[1]), "+f"(d[2]), "+f"(d[3])
        : "r"(a[0]), "r"(a[1]), "r"(a[2]), "r"(a[3]), "r"(b0), "r"(b1));
}
#define CP_ASYNC16(dst, src) \
    asm volatile("cp.async.cg.shared.global [%0], [%1], 16;" \
                 :: "r"(dst), "l"(src) : "memory")
#define CP_COMMIT() asm volatile("cp.async.commit_group;" ::: "memory")
#define CP_WAIT0()  asm volatile("cp.async.wait_group 0;" ::: "memory")
#define CP_WAIT1()  asm volatile("cp.async.wait_group 1;" ::: "memory")

static __device__ __forceinline__ uint32_t pkh(float a, float b) {
    __half2 h2 = __floats2half2_rn(a, b);
    return *reinterpret_cast<uint32_t*>(&h2);
}

// ---------------------------------------------------------------- W prep
__global__ void prep_w_kernel(const float* __restrict__ w1a,
                              const float* __restrict__ w1b) {
    int idx = blockIdx.x * 256 + threadIdx.x;      // 0..262143
    int arr = idx >> 17;
    int rem = idx & 131071;
    int c  = rem >> 14;
    int n  = (rem >> 6) & 255;
    int kk = rem & 63;
    const float* w = arr ? w1b : w1a;
    float f = w[(size_t)(c * 64 + kk) * HH + n];
    __half hi = __float2half_rn(f);
    __half lo = __float2half_rn(f - __half2float(hi));
    uint32_t off = (uint32_t)c * 32768u + SWZ((uint32_t)(n * 128 + kk * 2));
    *(__half*)((char*)g_whi[arr] + off) = hi;
    *(__half*)((char*)g_wlo[arr] + off) = lo;
}

// ---------------------------------------------------------------- fused GEMM
// 512 threads, 16 warps: warp grid 4(M) x 4(N), warp tile 32x64.
// acc = x_fp16 * (wh + wl)   (W exactly split in fp16; only x rounded once)
template <int PHASE>
__global__ __launch_bounds__(512, 1)
void gemm_mlp_kernel(const float* __restrict__ obj, const float* __restrict__ geo,
                     const float* __restrict__ b1, const float* __restrict__ w2,
                     const float* __restrict__ b2, float* __restrict__ outv) {
    extern __shared__ char smraw[];
    char* sm = (char*)(((uintptr_t)smraw + 1023) & ~(uintptr_t)1023);
    __shared__ float s_b1[HH], s_w2[HH];
    __shared__ float red[128][5];
    __shared__ float rowlogit[128];

    const int t = threadIdx.x;
    const int wid = t >> 5, lane = t & 31;
    const int wm = wid >> 2;           // 0..3  (M warp)
    const int wn = wid & 3;            // 0..3  (N warp)
    const uint32_t smb = smem_u32(sm);

    if (t < HH) { s_b1[t] = b1[t]; s_w2[t] = w2[t]; }

    const char* wsrcH = (const char*)g_whi[PHASE];
    const char* wsrcL = (const char*)g_wlo[PHASE];

    const int rsub = t >> 4;          // 0..31
    const int f4   = t & 15;

    float acc[2][8][4];
#pragma unroll
    for (int a = 0; a < 2; a++)
#pragma unroll
        for (int b = 0; b < 8; b++)
#pragma unroll
            for (int cq = 0; cq < 4; cq++) acc[a][b][cq] = 0.f;

    uint2 xp[4];
    auto buildX = [&](int c) {
#pragma unroll
        for (int m = 0; m < 4; m++) {
            const int row = m * 32 + rsub;
            float4 x;
            if (PHASE == 0) {
                int pl = row >> 3, r = row & 7;
                int p = blockIdx.x * 16 + pl;
                int i = p >> 7, j = p & 127;
                const float4 a = *(const float4*)(obj + (size_t)(r * NN + i) * DD
                                                  + c * KC + f4 * 4);
                const float4 b = *(const float4*)(obj + (size_t)(r * NN + j) * DD
                                                  + c * KC + f4 * 4);
                const float4 g4 = *(const float4*)(geo
                    + (size_t)((r * NN + i) * NN + j) * DD + c * KC + f4 * 4);
                x.x = fmaf(a.x, b.x, g4.x);
                x.y = fmaf(a.y, b.y, g4.y);
                x.z = fmaf(a.z, b.z, g4.z);
                x.w = fmaf(a.w, b.w, g4.w);
            } else {
                int g = blockIdx.x * 128 + row;
                const float4 a = *(const float4*)(g_pf + (g >> 6) * DD
                                                  + c * KC + f4 * 4);
                const float4 b = *(const float4*)(g_pf + (g & 63) * DD
                                                  + c * KC + f4 * 4);
                x.x = a.x * b.x; x.y = a.y * b.y;
                x.z = a.z * b.z; x.w = a.w * b.w;
            }
            xp[m].x = pkh(x.x, x.y);
            xp[m].y = pkh(x.z, x.w);
        }
    };
    auto stageStore = [&](char* bs, uint32_t bsb, int c) {
#pragma unroll
        for (int m = 0; m < 4; m++) {
            const uint32_t boff = SWZ((uint32_t)((m * 32 + rsub) * 128 + f4 * 8));
            *(uint2*)(bs + OFF_A + boff) = xp[m];
        }
        const char* sH = wsrcH + c * 32768;
        const char* sL = wsrcL + c * 32768;
#pragma unroll
        for (int m = 0; m < 4; m++) {
            uint32_t o = (uint32_t)(m * 8192 + t * 16);
            CP_ASYNC16(bsb + OFF_BHI + o, sH + o);
            CP_ASYNC16(bsb + OFF_BLO + o, sL + o);
        }
        CP_COMMIT();
    };

    const uint32_t aRow = (uint32_t)(wm * 32 + (lane & 15));
    const uint32_t nRow = (uint32_t)(wn * 64 + (lane & 15));
    const uint32_t kbL  = (uint32_t)((lane >> 4) * 16);

    buildX(0);
    stageStore(sm, smb, 0);
    buildX(1);

#pragma unroll 1
    for (int c = 0; c < NCH; c++) {
        const int st = c & 1;
        const uint32_t sbb = smb + st * STG;
        if (c + 1 < NCH) {
            stageStore(sm + (st ^ 1) * STG, smb + (st ^ 1) * STG, c + 1);
            CP_WAIT1();
        } else {
            CP_WAIT0();
        }
        __syncthreads();
        const uint32_t sA = sbb + OFF_A;
        const uint32_t sBhi = sbb + OFF_BHI, sBlo = sbb + OFF_BLO;
#pragma unroll
        for (int ks = 0; ks < 4; ks++) {
            const uint32_t kbase = ks * 32 + kbL;
            uint32_t ah[2][4];
#pragma unroll
            for (int mt = 0; mt < 2; mt++) {
                uint32_t off = SWZ((aRow + mt * 16) * 128 + kbase);
                ldsm4(ah[mt], sA + off);
            }
#pragma unroll
            for (int nh = 0; nh < 2; nh++) {
                uint32_t bh[2][4], bl[2][4];
#pragma unroll
                for (int p = 0; p < 2; p++) {
                    uint32_t off = SWZ((nRow + nh * 32 + p * 16) * 128 + kbase);
                    ldsm4(bh[p], sBhi + off);
                    ldsm4(bl[p], sBlo + off);
                }
#pragma unroll
                for (int mt = 0; mt < 2; mt++)
#pragma unroll
                    for (int p = 0; p < 2; p++)
#pragma unroll
                        for (int e = 0; e < 2; e++) {
                            float* d = acc[mt][nh * 4 + p * 2 + e];
                            mma16816(d, ah[mt], bh[p][e], bh[p][e + 2]);
                            mma16816(d, ah[mt], bl[p][e], bl[p][e + 2]);
                        }
            }
        }
        if (c + 2 < NCH) buildX(c + 2);
        __syncthreads();
    }

    // ---- epilogue: bias, relu, dot w2 ----
#pragma unroll
    for (int mt = 0; mt < 2; mt++) {
        float ps0 = 0.f, ps1 = 0.f;
#pragma unroll
        for (int nt = 0; nt < 8; nt++) {
            int h = wn * 64 + nt * 8 + (lane & 3) * 2;
            float b0 = s_b1[h],  w0 = s_w2[h];
            float b1v = s_b1[h + 1], w1v = s_w2[h + 1];
            ps0 = fmaf(fmaxf(acc[mt][nt][0] + b0, 0.f),  w0,  ps0);
            ps0 = fmaf(fmaxf(acc[mt][nt][1] + b1v, 0.f), w1v, ps0);
            ps1 = fmaf(fmaxf(acc[mt][nt][2] + b0, 0.f),  w0,  ps1);
            ps1 = fmaf(fmaxf(acc[mt][nt][3] + b1v, 0.f), w1v, ps1);
        }
        ps0 += __shfl_xor_sync(0xffffffffu, ps0, 1);
        ps0 += __shfl_xor_sync(0xffffffffu, ps0, 2);
        ps1 += __shfl_xor_sync(0xffffffffu, ps1, 1);
        ps1 += __shfl_xor_sync(0xffffffffu, ps1, 2);
        if ((lane & 3) == 0) {
            int r0 = wm * 32 + mt * 16 + (lane >> 2);
            red[r0][wn] = ps0;
            red[r0 + 8][wn] = ps1;
        }
    }
    __syncthreads();
    if (t < 128) rowlogit[t] = red[t][0] + red[t][1] + red[t][2] + red[t][3];
    __syncthreads();
    if (PHASE == 0) {
        if (t < 16) {
            float s = 0.f;
#pragma unroll
            for (int r = 0; r < 8; r++) s += rowlogit[t * 8 + r];
            outv[blockIdx.x * 16 + t] = s * 0.125f + b2[0];
        }
    } else {
        if (t < 128) outv[blockIdx.x * 128 + t] = rowlogit[t] + b2[0];
    }
}

// ---------------------------------------------------------------- threshold
// Bisect T so count(approx logit > T) ~ 256; compact those indices to g_cand.
// The exact top-64 is contained: E64 - E256 >> 2*(fp16 logit error).
__global__ __launch_bounds__(1024) void thresh_kernel(const float* __restrict__ logits,
                                                      const float* __restrict__ mask) {
    const int t = threadIdx.x;
    const int wid = t >> 5, lane = t & 31;
    float v[16];
#pragma unroll
    for (int u = 0; u < 16; u++) {
        int p = u * 1024 + t;
        v[u] = (mask[p] != 0.f) ? logits[p] : -3.4e38f;
    }
    // block min/max over unmasked values
    float mymax = -3.4e38f, mymin = 3.4e38f;
#pragma unroll
    for (int u = 0; u < 16; u++) {
        mymax = fmaxf(mymax, v[u]);
        if (v[u] > -1e38f) mymin = fminf(mymin, v[u]);
    }
    __shared__ float smax[32], smin[32];
    __shared__ int scnt[32];
    __shared__ float s_lo, s_hi;
#pragma unroll
    for (int o = 16; o > 0; o >>= 1) {
        mymax = fmaxf(mymax, __shfl_xor_sync(0xffffffffu, mymax, o));
        mymin = fminf(mymin, __shfl_xor_sync(0xffffffffu, mymin, o));
    }
    if (lane == 0) { smax[wid] = mymax; smin[wid] = mymin; }
    __syncthreads();
    if (t == 0) {
        float gx = smax[0], gn = smin[0];
        for (int w = 1; w < 32; w++) { gx = fmaxf(gx, smax[w]); gn = fminf(gn, smin[w]); }
        s_lo = gn - 1.0f;          // count(>lo) = all unmasked >= 256
        s_hi = gx;                 // count(>hi) = 0
    }
    __syncthreads();
    float lo = s_lo, hi = s_hi;

    __shared__ int s_c;
    for (int it = 0; it < 24; it++) {
        float mid = 0.5f * (lo + hi);
        int c = 0;
#pragma unroll
        for (int u = 0; u < 16; u++) c += (v[u] > mid);
        c = __reduce_add_sync(0xffffffffu, c);
        if (lane == 0) scnt[wid] = c;
        __syncthreads();
        if (wid == 0) {
            int cc = __reduce_add_sync(0xffffffffu, scnt[lane]);
            if (lane == 0) s_c = cc;
        }
        __syncthreads();
        int c_all = s_c;
        if (c_all >= 256) lo = mid; else hi = mid;
        __syncthreads();
    }
    // compact indices with v > lo  (count in [256, ~257+], <= NCAP)
    __shared__ int s_cnt;
    if (t == 0) s_cnt = 0;
    __syncthreads();
#pragma unroll
    for (int u = 0; u < 16; u++) {
        if (v[u] > lo) {
            int pos = atomicAdd(&s_cnt, 1);
            if (pos < NCAP) g_cand[pos] = u * 1024 + t;
        }
    }
    __syncthreads();
    if (t == 0) g_ncand = (s_cnt < NCAP) ? s_cnt : NCAP;
}

// ---------------------------------------------------------------- refine
// Exact fp32 r-mean logit per candidate. Batched w1 loads (MLP=16).
__global__ __launch_bounds__(256) void refine_kernel(const float* __restrict__ obj,
                                                     const float* __restrict__ geo,
                                                     const float* __restrict__ w1,
                                                     const float* __restrict__ b1,
                                                     const float* __restrict__ w2,
                                                     const float* __restrict__ b2) {
    __shared__ int s_ind;
    __shared__ float xs[RR][DD];
    __shared__ float rsum[8][RR];
    __shared__ float rtot[RR];
    const int ci = blockIdx.x;
    const int t = threadIdx.x;
    const int wid = t >> 5, lane = t & 31;
    if (t == 0) s_ind = (ci < g_ncand) ? g_cand[ci] : -1;
    __syncthreads();
    const int ind = s_ind;
    if (ind < 0) {
        if (t == 0) g_cand_logit[ci] = -3.4e38f;
        return;
    }
    const int i = ind >> 7, j = ind & 127;

#pragma unroll
    for (int r = 0; r < RR; r++)
        for (int d = t; d < DD; d += 256)
            xs[r][d] = fmaf(obj[(size_t)(r * NN + i) * DD + d],
                            obj[(size_t)(r * NN + j) * DD + d],
                            geo[(size_t)((r * NN + i) * NN + j) * DD + d]);
    __syncthreads();

    float z[RR];
#pragma unroll
    for (int r = 0; r < RR; r++) z[r] = 0.f;
    const int h = t;
#pragma unroll 1
    for (int d0 = 0; d0 < DD; d0 += 16) {
        float wv[16];
#pragma unroll
        for (int q = 0; q < 16; q++) wv[q] = w1[(size_t)(d0 + q) * HH + h];
#pragma unroll
        for (int q = 0; q < 16; q++)
#pragma unroll
            for (int r = 0; r < RR; r++)
                z[r] = fmaf(xs[r][d0 + q], wv[q], z[r]);
    }
    const float bb = b1[h], ww = w2[h];
#pragma unroll
    for (int r = 0; r < RR; r++) {
        float v = fmaxf(z[r] + bb, 0.f) * ww;
#pragma unroll
        for (int o = 16; o > 0; o >>= 1) v += __shfl_xor_sync(0xffffffffu, v, o);
        if (lane == 0) rsum[wid][r] = v;
    }
    __syncthreads();
    if (t < RR) {
        float s = 0.f;
#pragma unroll
        for (int w = 0; w < 8; w++) s += rsum[w][t];
        rtot[t] = s;
    }
    __syncthreads();
    if (t == 0) {
        float s = 0.f;
#pragma unroll
        for (int r = 0; r < RR; r++) s += rtot[r];
        g_cand_logit[ci] = s * 0.125f + b2[0];
    }
}

// ---------------------------------------------------------------- final top-64
// Single warp; 512 (value, index) register-resident; value desc, index asc.
__global__ __launch_bounds__(32) void final_topk_kernel(float* __restrict__ out_inds) {
    const int lane = threadIdx.x;
    float v[16];
    int idx[16];
#pragma unroll
    for (int u = 0; u < 16; u++) {
        v[u] = g_cand_logit[lane * 16 + u];
        idx[u] = (v[u] > -1e38f) ? g_cand[lane * 16 + u] : (1 << 30);
    }
    float lmax = -3.4e38f; int li = 1 << 30, ls = 0;
#pragma unroll
    for (int u = 0; u < 16; u++)
        if (v[u] > lmax || (v[u] == lmax && idx[u] < li)) { lmax = v[u]; li = idx[u]; ls = u; }

    for (int sel = 0; sel < KTOP; sel++) {
        float bv = lmax; int bi = li;
#pragma unroll
        for (int o = 16; o > 0; o >>= 1) {
            float ov = __shfl_xor_sync(0xffffffffu, bv, o);
            int oi = __shfl_xor_sync(0xffffffffu, bi, o);
            if (ov > bv || (ov == bv && oi < bi)) { bv = ov; bi = oi; }
        }
        if (lane == 0) { g_topk[sel] = bi; out_inds[sel] = (float)bi; }
        if (bi == li) {                    // this lane owned the winner
            v[ls] = -3.4e38f; idx[ls] = 1 << 30;
            lmax = -3.4e38f; li = 1 << 30; ls = 0;
#pragma unroll
            for (int u = 0; u < 16; u++)
                if (v[u] > lmax || (v[u] == lmax && idx[u] < li)) { lmax = v[u]; li = idx[u]; ls = u; }
        }
    }
}

// ---------------------------------------------------------------- gather
__global__ void gather_pf_kernel(const float* __restrict__ obj,
                                 const float* __restrict__ geo) {
    const int b = blockIdx.x;
    const int ind = g_topk[b];
    const int i = ind >> 7, j = ind & 127;
    const int d = threadIdx.x * 4;
    float4 a = make_float4(0.f, 0.f, 0.f, 0.f);
#pragma unroll
    for (int r = 0; r < RR; r++) {
        const float4 oi = *(const float4*)&obj[(size_t)(r * NN + i) * DD + d];
        const float4 oj = *(const float4*)&obj[(size_t)(r * NN + j) * DD + d];
        const float4 g4 = *(const float4*)&geo[(size_t)((r * NN + i) * NN + j) * DD + d];
        a.x += fmaf(oi.x, oj.x, g4.x);
        a.y += fmaf(oi.y, oj.y, g4.y);
        a.z += fmaf(oi.z, oj.z, g4.z);
        a.w += fmaf(oi.w, oj.w, g4.w);
    }
    a.x *= (1.f / RR); a.y *= (1.f / RR); a.z *= (1.f / RR); a.w *= (1.f / RR);
    *(float4*)&g_pf[b * DD + d] = a;
}

// ---------------------------------------------------------------- launch
extern "C" void kernel_launch(void* const* d_in, const int* in_sizes, int n_in,
                              void* d_out, int out_size) {
    const float* obj  = (const float*)d_in[0];
    const float* geo  = (const float*)d_in[1];
    const float* mask = (const float*)d_in[2];
    const float* w1a  = (const float*)d_in[3];
    const float* b1a  = (const float*)d_in[4];
    const float* w2a  = (const float*)d_in[5];
    const float* b2a  = (const float*)d_in[6];
    const float* w1b  = (const float*)d_in[7];
    const float* b1b  = (const float*)d_in[8];
    const float* w2b  = (const float*)d_in[9];
    const float* b2b  = (const float*)d_in[10];
    float* out = (float*)d_out;

    const int dyn = 2 * STG + 1024;  // +1024 for manual alignment
    cudaFuncSetAttribute(gemm_mlp_kernel<0>,
                         cudaFuncAttributeMaxDynamicSharedMemorySize, dyn);
    cudaFuncSetAttribute(gemm_mlp_kernel<1>,
                         cudaFuncAttributeMaxDynamicSharedMemorySize, dyn);

    prep_w_kernel<<<1024, 256>>>(w1a, w1b);
    gemm_mlp_kernel<0><<<NPAIR / 16, 512, dyn>>>(obj, geo, b1a, w2a, b2a, out);
    thresh_kernel<<<1, 1024>>>(out, mask);
    refine_kernel<<<NCAP, 256>>>(obj, geo, w1a, b1a, w2a, b2a);
    final_topk_kernel<<<1, 32>>>(out + NPAIR + KTOP * KTOP);
    gather_pf_kernel<<<KTOP, 128>>>(obj, geo);
    gemm_mlp_kernel<1><<<KTOP * KTOP / 128, 512, dyn>>>(obj, geo, b1b, w2b, b2b,
                                                        out + NPAIR);
}

// round 14
// speedup vs baseline: 1.1543x; 1.1543x over previous
#include <cuda_runtime.h>
#include <cuda_fp16.h>
#include <cstdint>
#include <math.h>

// ---------------------------------------------------------------- constants
#define RR 8
#define NN 128
#define DD 512
#define HH 256
#define KTOP 64
#define NCAP 256               // candidate capacity
#define NPAIR (NN*NN)          // 16384
#define KC 64                  // K per chunk (64 fp16 = 128B rows, SW128 atom)
#define NCH 8                  // 512 / 64
#define STG 81920              // bytes per smem stage (A + B_hi + B_lo)
#define OFF_A   0              // 16384 B  (128 rows x 128B)
#define OFF_BHI 16384          // 32768 B  (256 rows x 128B)
#define OFF_BLO 49152          // 32768 B
#define SWZ(o) ((o) ^ (((o) >> 3) & 0x70))

// ---------------------------------------------------------------- scratch
__device__ float g_pf[KTOP * DD];                 // gathered mean pair feats
__device__ int   g_topk[KTOP];
__device__ int   g_cand[NCAP];
__device__ float g_cand_logit[NCAP];
__device__ int   g_ncand;
__device__ __align__(16) __half g_whi[2][NCH * 16384]; // W split hi (fp16)
__device__ __align__(16) __half g_wlo[2][NCH * 16384]; // W split lo (fp16)

// ---------------------------------------------------------------- helpers
static __device__ __forceinline__ uint32_t smem_u32(const void* p) {
    uint32_t a;
    asm("{ .reg .u64 t; cvta.to.shared.u64 t, %1; cvt.u32.u64 %0, t; }"
        : "=r"(a) : "l"(p));
    return a;
}
static __device__ __forceinline__ void ldsm4(uint32_t* r, uint32_t addr) {
    asm volatile("ldmatrix.sync.aligned.m8n8.x4.shared.b16 {%0,%1,%2,%3}, [%4];"
                 : "=r"(r[0]), "=r"(r[1]), "=r"(r[2]), "=r"(r[3]) : "r"(addr));
}
static __device__ __forceinline__ void mma16816(float* d, const uint32_t* a,
                                                uint32_t b0, uint32_t b1) {
    asm volatile(
        "mma.sync.aligned.m16n8k16.row.col.f32.f16.f16.f32 "
        "{%0,%1,%2,%3}, {%4,%5,%6,%7}, {%8,%9}, {%0,%1,%2,%3};"
        : "+f"(d[0]), "+f"(d[1]), "+f"(d[2]), "+f"(d[3])
        : "r"(a[0]), "r"(a[1]), "r"(a[2]), "r"(a[3]), "r"(b0), "r"(b1));
}
#define CP_ASYNC16(dst, src) \
    asm volatile("cp.async.cg.shared.global [%0], [%1], 16;" \
                 :: "r"(dst), "l"(src) : "memory")
#define CP_COMMIT() asm volatile("cp.async.commit_group;" ::: "memory")
#define CP_WAIT0()  asm volatile("cp.async.wait_group 0;" ::: "memory")
#define CP_WAIT1()  asm volatile("cp.async.wait_group 1;" ::: "memory")

static __device__ __forceinline__ uint32_t pkh(float a, float b) {
    __half2 h2 = __floats2half2_rn(a, b);
    return *reinterpret_cast<uint32_t*>(&h2);
}

// ---------------------------------------------------------------- W prep
__global__ void prep_w_kernel(const float* __restrict__ w1a,
                              const float* __restrict__ w1b) {
    int idx = blockIdx.x * 256 + threadIdx.x;      // 0..262143
    int arr = idx >> 17;
    int rem = idx & 131071;
    int c  = rem >> 14;
    int n  = (rem >> 6) & 255;
    int kk = rem & 63;
    const float* w = arr ? w1b : w1a;
    float f = w[(size_t)(c * 64 + kk) * HH + n];
    __half hi = __float2half_rn(f);
    __half lo = __float2half_rn(f - __half2float(hi));
    uint32_t off = (uint32_t)c * 32768u + SWZ((uint32_t)(n * 128 + kk * 2));
    *(__half*)((char*)g_whi[arr] + off) = hi;
    *(__half*)((char*)g_wlo[arr] + off) = lo;
}

// ---------------------------------------------------------------- fused GEMM
// 512 threads, 16 warps: warp grid 4(M) x 4(N), warp tile 32x64.
// acc = x_fp16 * (wh + wl)   (W exactly split in fp16; only x rounded once)
template <int PHASE>
__global__ __launch_bounds__(512, 1)
void gemm_mlp_kernel(const float* __restrict__ obj, const float* __restrict__ geo,
                     const float* __restrict__ b1, const float* __restrict__ w2,
                     const float* __restrict__ b2, float* __restrict__ outv) {
    extern __shared__ char smraw[];
    char* sm = (char*)(((uintptr_t)smraw + 1023) & ~(uintptr_t)1023);
    __shared__ float s_b1[HH], s_w2[HH];
    __shared__ float red[128][5];
    __shared__ float rowlogit[128];

    const int t = threadIdx.x;
    const int wid = t >> 5, lane = t & 31;
    const int wm = wid >> 2;           // 0..3  (M warp)
    const int wn = wid & 3;            // 0..3  (N warp)
    const uint32_t smb = smem_u32(sm);

    if (t < HH) { s_b1[t] = b1[t]; s_w2[t] = w2[t]; }

    const char* wsrcH = (const char*)g_whi[PHASE];
    const char* wsrcL = (const char*)g_wlo[PHASE];

    const int rsub = t >> 4;          // 0..31
    const int f4   = t & 15;

    float acc[2][8][4];
#pragma unroll
    for (int a = 0; a < 2; a++)
#pragma unroll
        for (int b = 0; b < 8; b++)
#pragma unroll
            for (int cq = 0; cq < 4; cq++) acc[a][b][cq] = 0.f;

    uint2 xp[4];
    auto buildX = [&](int c) {
#pragma unroll
        for (int m = 0; m < 4; m++) {
            const int row = m * 32 + rsub;
            float4 x;
            if (PHASE == 0) {
                int pl = row >> 3, r = row & 7;
                int p = blockIdx.x * 16 + pl;
                int i = p >> 7, j = p & 127;
                const float4 a = *(const float4*)(obj + (size_t)(r * NN + i) * DD
                                                  + c * KC + f4 * 4);
                const float4 b = *(const float4*)(obj + (size_t)(r * NN + j) * DD
                                                  + c * KC + f4 * 4);
                const float4 g4 = *(const float4*)(geo
                    + (size_t)((r * NN + i) * NN + j) * DD + c * KC + f4 * 4);
                x.x = fmaf(a.x, b.x, g4.x);
                x.y = fmaf(a.y, b.y, g4.y);
                x.z = fmaf(a.z, b.z, g4.z);
                x.w = fmaf(a.w, b.w, g4.w);
            } else {
                int g = blockIdx.x * 128 + row;
                const float4 a = *(const float4*)(g_pf + (g >> 6) * DD
                                                  + c * KC + f4 * 4);
                const float4 b = *(const float4*)(g_pf + (g & 63) * DD
                                                  + c * KC + f4 * 4);
                x.x = a.x * b.x; x.y = a.y * b.y;
                x.z = a.z * b.z; x.w = a.w * b.w;
            }
            xp[m].x = pkh(x.x, x.y);
            xp[m].y = pkh(x.z, x.w);
        }
    };
    auto stageStore = [&](char* bs, uint32_t bsb, int c) {
#pragma unroll
        for (int m = 0; m < 4; m++) {
            const uint32_t boff = SWZ((uint32_t)((m * 32 + rsub) * 128 + f4 * 8));
            *(uint2*)(bs + OFF_A + boff) = xp[m];
        }
        const char* sH = wsrcH + c * 32768;
        const char* sL = wsrcL + c * 32768;
#pragma unroll
        for (int m = 0; m < 4; m++) {
            uint32_t o = (uint32_t)(m * 8192 + t * 16);
            CP_ASYNC16(bsb + OFF_BHI + o, sH + o);
            CP_ASYNC16(bsb + OFF_BLO + o, sL + o);
        }
        CP_COMMIT();
    };

    const uint32_t aRow = (uint32_t)(wm * 32 + (lane & 15));
    const uint32_t nRow = (uint32_t)(wn * 64 + (lane & 15));
    const uint32_t kbL  = (uint32_t)((lane >> 4) * 16);

    buildX(0);
    stageStore(sm, smb, 0);
    buildX(1);

#pragma unroll 1
    for (int c = 0; c < NCH; c++) {
        const int st = c & 1;
        const uint32_t sbb = smb + st * STG;
        if (c + 1 < NCH) {
            stageStore(sm + (st ^ 1) * STG, smb + (st ^ 1) * STG, c + 1);
            CP_WAIT1();
        } else {
            CP_WAIT0();
        }
        __syncthreads();
        const uint32_t sA = sbb + OFF_A;
        const uint32_t sBhi = sbb + OFF_BHI, sBlo = sbb + OFF_BLO;
#pragma unroll
        for (int ks = 0; ks < 4; ks++) {
            const uint32_t kbase = ks * 32 + kbL;
            uint32_t ah[2][4];
#pragma unroll
            for (int mt = 0; mt < 2; mt++) {
                uint32_t off = SWZ((aRow + mt * 16) * 128 + kbase);
                ldsm4(ah[mt], sA + off);
            }
#pragma unroll
            for (int nh = 0; nh < 2; nh++) {
                uint32_t bh[2][4], bl[2][4];
#pragma unroll
                for (int p = 0; p < 2; p++) {
                    uint32_t off = SWZ((nRow + nh * 32 + p * 16) * 128 + kbase);
                    ldsm4(bh[p], sBhi + off);
                    ldsm4(bl[p], sBlo + off);
                }
#pragma unroll
                for (int mt = 0; mt < 2; mt++)
#pragma unroll
                    for (int p = 0; p < 2; p++)
#pragma unroll
                        for (int e = 0; e < 2; e++) {
                            float* d = acc[mt][nh * 4 + p * 2 + e];
                            mma16816(d, ah[mt], bh[p][e], bh[p][e + 2]);
                            mma16816(d, ah[mt], bl[p][e], bl[p][e + 2]);
                        }
            }
        }
        if (c + 2 < NCH) buildX(c + 2);
        __syncthreads();
    }

    // ---- epilogue: bias, relu, dot w2 ----
#pragma unroll
    for (int mt = 0; mt < 2; mt++) {
        float ps0 = 0.f, ps1 = 0.f;
#pragma unroll
        for (int nt = 0; nt < 8; nt++) {
            int h = wn * 64 + nt * 8 + (lane & 3) * 2;
            float b0 = s_b1[h],  w0 = s_w2[h];
            float b1v = s_b1[h + 1], w1v = s_w2[h + 1];
            ps0 = fmaf(fmaxf(acc[mt][nt][0] + b0, 0.f),  w0,  ps0);
            ps0 = fmaf(fmaxf(acc[mt][nt][1] + b1v, 0.f), w1v, ps0);
            ps1 = fmaf(fmaxf(acc[mt][nt][2] + b0, 0.f),  w0,  ps1);
            ps1 = fmaf(fmaxf(acc[mt][nt][3] + b1v, 0.f), w1v, ps1);
        }
        ps0 += __shfl_xor_sync(0xffffffffu, ps0, 1);
        ps0 += __shfl_xor_sync(0xffffffffu, ps0, 2);
        ps1 += __shfl_xor_sync(0xffffffffu, ps1, 1);
        ps1 += __shfl_xor_sync(0xffffffffu, ps1, 2);
        if ((lane & 3) == 0) {
            int r0 = wm * 32 + mt * 16 + (lane >> 2);
            red[r0][wn] = ps0;
            red[r0 + 8][wn] = ps1;
        }
    }
    __syncthreads();
    if (t < 128) rowlogit[t] = red[t][0] + red[t][1] + red[t][2] + red[t][3];
    __syncthreads();
    if (PHASE == 0) {
        if (t < 16) {
            float s = 0.f;
#pragma unroll
            for (int r = 0; r < 8; r++) s += rowlogit[t * 8 + r];
            outv[blockIdx.x * 16 + t] = s * 0.125f + b2[0];
        }
    } else {
        if (t < 128) outv[blockIdx.x * 128 + t] = rowlogit[t] + b2[0];
    }
}

// ---------------------------------------------------------------- threshold
// Bisect T so count(approx logit > T) lands in [96, 240]; compact to g_cand.
// fp16 logit error (~5e-4) perturbs boundary ranks by ~1; 32+ ranks margin.
__global__ __launch_bounds__(1024) void thresh_kernel(const float* __restrict__ logits,
                                                      const float* __restrict__ mask) {
    const int t = threadIdx.x;
    const int wid = t >> 5, lane = t & 31;
    float v[16];
#pragma unroll
    for (int u = 0; u < 16; u++) {
        int p = u * 1024 + t;
        v[u] = (mask[p] != 0.f) ? logits[p] : -3.4e38f;
    }
    float mymax = -3.4e38f, mymin = 3.4e38f;
#pragma unroll
    for (int u = 0; u < 16; u++) {
        mymax = fmaxf(mymax, v[u]);
        if (v[u] > -1e38f) mymin = fminf(mymin, v[u]);
    }
    __shared__ float smax[32], smin[32];
    __shared__ int scnt[32];
    __shared__ float s_lo, s_hi;
#pragma unroll
    for (int o = 16; o > 0; o >>= 1) {
        mymax = fmaxf(mymax, __shfl_xor_sync(0xffffffffu, mymax, o));
        mymin = fminf(mymin, __shfl_xor_sync(0xffffffffu, mymin, o));
    }
    if (lane == 0) { smax[wid] = mymax; smin[wid] = mymin; }
    __syncthreads();
    if (t == 0) {
        float gx = smax[0], gn = smin[0];
        for (int w = 1; w < 32; w++) { gx = fmaxf(gx, smax[w]); gn = fminf(gn, smin[w]); }
        s_lo = gn - 1.0f;
        s_hi = gx;
    }
    __syncthreads();
    float lo = s_lo, hi = s_hi;

    __shared__ int s_c;
    for (int it = 0; it < 24; it++) {
        float mid = 0.5f * (lo + hi);
        int c = 0;
#pragma unroll
        for (int u = 0; u < 16; u++) c += (v[u] > mid);
        c = __reduce_add_sync(0xffffffffu, c);
        if (lane == 0) scnt[wid] = c;
        __syncthreads();
        if (wid == 0) {
            int cc = __reduce_add_sync(0xffffffffu, scnt[lane]);
            if (lane == 0) s_c = cc;
        }
        __syncthreads();
        int c_all = s_c;
        if (c_all >= 96 && c_all <= 240) { lo = mid; break; }
        if (c_all > 240) lo = mid; else hi = mid;
        __syncthreads();
    }
    // compact indices with v > lo
    __shared__ int s_cnt;
    __syncthreads();
    if (t == 0) s_cnt = 0;
    __syncthreads();
#pragma unroll
    for (int u = 0; u < 16; u++) {
        if (v[u] > lo) {
            int pos = atomicAdd(&s_cnt, 1);
            if (pos < NCAP) g_cand[pos] = u * 1024 + t;
        }
    }
    __syncthreads();
    if (t == 0) g_ncand = (s_cnt < NCAP) ? s_cnt : NCAP;
}

// ---------------------------------------------------------------- refine
// Exact fp32 r-mean logit per candidate. w1 smem-tiled (coalesced float4),
// each thread owns one h, 8 r-accumulators in registers.
__global__ __launch_bounds__(256) void refine_kernel(const float* __restrict__ obj,
                                                     const float* __restrict__ geo,
                                                     const float* __restrict__ w1,
                                                     const float* __restrict__ b1,
                                                     const float* __restrict__ w2,
                                                     const float* __restrict__ b2) {
    __shared__ int s_ind;
    __shared__ __align__(16) float xs[RR][DD];       // 16 KB
    __shared__ __align__(16) float ws[16][HH];       // 16 KB
    __shared__ float rsum[8][RR];
    __shared__ float rtot[RR];
    const int ci = blockIdx.x;
    const int t = threadIdx.x;
    const int wid = t >> 5, lane = t & 31;
    if (t == 0) s_ind = (ci < g_ncand) ? g_cand[ci] : -1;
    __syncthreads();
    const int ind = s_ind;
    if (ind < 0) {
        if (t == 0) g_cand_logit[ci] = -3.4e38f;
        return;
    }
    const int i = ind >> 7, j = ind & 127;

#pragma unroll
    for (int r = 0; r < RR; r++)
        for (int d = t; d < DD; d += 256)
            xs[r][d] = fmaf(obj[(size_t)(r * NN + i) * DD + d],
                            obj[(size_t)(r * NN + j) * DD + d],
                            geo[(size_t)((r * NN + i) * NN + j) * DD + d]);

    float z[RR];
#pragma unroll
    for (int r = 0; r < RR; r++) z[r] = 0.f;
    const int h = t;
#pragma unroll 1
    for (int d0 = 0; d0 < DD; d0 += 16) {
        __syncthreads();               // prev tile consumed (also covers xs build)
#pragma unroll
        for (int it = 0; it < 4; it++) {
            int idx = it * 256 + t;    // float4 id 0..1023
            int row = idx >> 6;        // 0..15
            int c4  = idx & 63;        // 0..63
            *(float4*)&ws[row][c4 * 4] =
                *(const float4*)&w1[(size_t)(d0 + row) * HH + c4 * 4];
        }
        __syncthreads();
#pragma unroll
        for (int q = 0; q < 16; q++) {
            float wv = ws[q][h];
#pragma unroll
            for (int r = 0; r < RR; r++)
                z[r] = fmaf(xs[r][d0 + q], wv, z[r]);
        }
    }
    const float bb = b1[h], ww = w2[h];
#pragma unroll
    for (int r = 0; r < RR; r++) {
        float v = fmaxf(z[r] + bb, 0.f) * ww;
#pragma unroll
        for (int o = 16; o > 0; o >>= 1) v += __shfl_xor_sync(0xffffffffu, v, o);
        if (lane == 0) rsum[wid][r] = v;
    }
    __syncthreads();
    if (t < RR) {
        float s = 0.f;
#pragma unroll
        for (int w = 0; w < 8; w++) s += rsum[w][t];
        rtot[t] = s;
    }
    __syncthreads();
    if (t == 0) {
        float s = 0.f;
#pragma unroll
        for (int r = 0; r < RR; r++) s += rtot[r];
        g_cand_logit[ci] = s * 0.125f + b2[0];
    }
}

// ---------------------------------------------------------------- final top-64
// Single warp; 256 (value, index) register-resident; value desc, index asc.
__global__ __launch_bounds__(32) void final_topk_kernel(float* __restrict__ out_inds) {
    const int lane = threadIdx.x;
    float v[8];
    int idx[8];
#pragma unroll
    for (int u = 0; u < 8; u++) {
        v[u] = g_cand_logit[lane * 8 + u];
        idx[u] = (v[u] > -1e38f) ? g_cand[lane * 8 + u] : (1 << 30);
    }
    float lmax = -3.4e38f; int li = 1 << 30, ls = 0;
#pragma unroll
    for (int u = 0; u < 8; u++)
        if (v[u] > lmax || (v[u] == lmax && idx[u] < li)) { lmax = v[u]; li = idx[u]; ls = u; }

    for (int sel = 0; sel < KTOP; sel++) {
        float bv = lmax; int bi = li;
#pragma unroll
        for (int o = 16; o > 0; o >>= 1) {
            float ov = __shfl_xor_sync(0xffffffffu, bv, o);
            int oi = __shfl_xor_sync(0xffffffffu, bi, o);
            if (ov > bv || (ov == bv && oi < bi)) { bv = ov; bi = oi; }
        }
        if (lane == 0) { g_topk[sel] = bi; out_inds[sel] = (float)bi; }
        if (bi == li) {                    // this lane owned the winner
            v[ls] = -3.4e38f; idx[ls] = 1 << 30;
            lmax = -3.4e38f; li = 1 << 30; ls = 0;
#pragma unroll
            for (int u = 0; u < 8; u++)
                if (v[u] > lmax || (v[u] == lmax && idx[u] < li)) { lmax = v[u]; li = idx[u]; ls = u; }
        }
    }
}

// ---------------------------------------------------------------- gather
__global__ void gather_pf_kernel(const float* __restrict__ obj,
                                 const float* __restrict__ geo) {
    const int b = blockIdx.x;
    const int ind = g_topk[b];
    const int i = ind >> 7, j = ind & 127;
    const int d = threadIdx.x * 4;
    float4 a = make_float4(0.f, 0.f, 0.f, 0.f);
#pragma unroll
    for (int r = 0; r < RR; r++) {
        const float4 oi = *(const float4*)&obj[(size_t)(r * NN + i) * DD + d];
        const float4 oj = *(const float4*)&obj[(size_t)(r * NN + j) * DD + d];
        const float4 g4 = *(const float4*)&geo[(size_t)((r * NN + i) * NN + j) * DD + d];
        a.x += fmaf(oi.x, oj.x, g4.x);
        a.y += fmaf(oi.y, oj.y, g4.y);
        a.z += fmaf(oi.z, oj.z, g4.z);
        a.w += fmaf(oi.w, oj.w, g4.w);
    }
    a.x *= (1.f / RR); a.y *= (1.f / RR); a.z *= (1.f / RR); a.w *= (1.f / RR);
    *(float4*)&g_pf[b * DD + d] = a;
}

// ---------------------------------------------------------------- launch
extern "C" void kernel_launch(void* const* d_in, const int* in_sizes, int n_in,
                              void* d_out, int out_size) {
    const float* obj  = (const float*)d_in[0];
    const float* geo  = (const float*)d_in[1];
    const float* mask = (const float*)d_in[2];
    const float* w1a  = (const float*)d_in[3];
    const float* b1a  = (const float*)d_in[4];
    const float* w2a  = (const float*)d_in[5];
    const float* b2a  = (const float*)d_in[6];
    const float* w1b  = (const float*)d_in[7];
    const float* b1b  = (const float*)d_in[8];
    const float* w2b  = (const float*)d_in[9];
    const float* b2b  = (const float*)d_in[10];
    float* out = (float*)d_out;

    const int dyn = 2 * STG + 1024;  // +1024 for manual alignment
    cudaFuncSetAttribute(gemm_mlp_kernel<0>,
                         cudaFuncAttributeMaxDynamicSharedMemorySize, dyn);
    cudaFuncSetAttribute(gemm_mlp_kernel<1>,
                         cudaFuncAttributeMaxDynamicSharedMemorySize, dyn);

    prep_w_kernel<<<1024, 256>>>(w1a, w1b);
    gemm_mlp_kernel<0><<<NPAIR / 16, 512, dyn>>>(obj, geo, b1a, w2a, b2a, out);
    thresh_kernel<<<1, 1024>>>(out, mask);
    refine_kernel<<<NCAP, 256>>>(obj, geo, w1a, b1a, w2a, b2a);
    final_topk_kernel<<<1, 32>>>(out + NPAIR + KTOP * KTOP);
    gather_pf_kernel<<<KTOP, 128>>>(obj, geo);
    gemm_mlp_kernel<1><<<KTOP * KTOP / 128, 512, dyn>>>(obj, geo, b1b, w2b, b2b,
                                                        out + NPAIR);
}

// round 15
// speedup vs baseline: 2.5846x; 2.2390x over previous
#include <cuda_runtime.h>
#include <cuda_fp16.h>
#include <cstdint>
#include <math.h>

// ---------------------------------------------------------------- constants
#define RR 8
#define NN 128
#define DD 512
#define HH 256
#define KTOP 64
#define NCAP 256               // candidate capacity
#define NPAIR (NN*NN)          // 16384
#define KC 64                  // K per chunk (64 fp16 = 128B rows, SW128 atom)
#define NCH 8                  // 512 / 64
#define STG 49152              // bytes per smem stage (A + B)
#define OFF_A 0                // 16384 B  (128 rows x 128B)
#define OFF_B 16384            // 32768 B  (256 rows x 128B)
#define SWZ(o) ((o) ^ (((o) >> 3) & 0x70))

// ---------------------------------------------------------------- scratch
__device__ float g_pf[KTOP * DD];                 // gathered mean pair feats
__device__ int   g_topk[KTOP];
__device__ int   g_cand[NCAP];
__device__ float g_cand_logit[NCAP];
__device__ int   g_ncand;
__device__ __align__(16) __half g_wh[2][NCH * 16384];  // W fp16, swizzled

// ---------------------------------------------------------------- helpers
static __device__ __forceinline__ uint32_t smem_u32(const void* p) {
    uint32_t a;
    asm("{ .reg .u64 t; cvta.to.shared.u64 t, %1; cvt.u32.u64 %0, t; }"
        : "=r"(a) : "l"(p));
    return a;
}
static __device__ __forceinline__ void ldsm4(uint32_t* r, uint32_t addr) {
    asm volatile("ldmatrix.sync.aligned.m8n8.x4.shared.b16 {%0,%1,%2,%3}, [%4];"
                 : "=r"(r[0]), "=r"(r[1]), "=r"(r[2]), "=r"(r[3]) : "r"(addr));
}
static __device__ __forceinline__ void mma16816(float* d, const uint32_t* a,
                                                uint32_t b0, uint32_t b1) {
    asm volatile(
        "mma.sync.aligned.m16n8k16.row.col.f32.f16.f16.f32 "
        "{%0,%1,%2,%3}, {%4,%5,%6,%7}, {%8,%9}, {%0,%1,%2,%3};"
        : "+f"(d[0]), "+f"(d[1]), "+f"(d[2]), "+f"(d[3])
        : "r"(a[0]), "r"(a[1]), "r"(a[2]), "r"(a[3]), "r"(b0), "r"(b1));
}
#define CP_ASYNC16(dst, src) \
    asm volatile("cp.async.cg.shared.global [%0], [%1], 16;" \
                 :: "r"(dst), "l"(src) : "memory")
#define CP_COMMIT() asm volatile("cp.async.commit_group;" ::: "memory")
#define CP_WAIT0()  asm volatile("cp.async.wait_group 0;" ::: "memory")
#define CP_WAIT1()  asm volatile("cp.async.wait_group 1;" ::: "memory")

static __device__ __forceinline__ uint32_t pkh(float a, float b) {
    __half2 h2 = __floats2half2_rn(a, b);
    return *reinterpret_cast<uint32_t*>(&h2);
}

// ---------------------------------------------------------------- W prep
// W1 (fp32 [512,256]) -> fp16, transposed to [n][k] per K-chunk, swizzled.
__global__ void prep_w_kernel(const float* __restrict__ w1a,
                              const float* __restrict__ w1b) {
    int idx = blockIdx.x * 256 + threadIdx.x;      // 0..262143
    int arr = idx >> 17;
    int rem = idx & 131071;
    int c  = rem >> 14;
    int n  = (rem >> 6) & 255;
    int kk = rem & 63;
    const float* w = arr ? w1b : w1a;
    float f = w[(size_t)(c * 64 + kk) * HH + n];
    uint32_t off = (uint32_t)c * 32768u + SWZ((uint32_t)(n * 128 + kk * 2));
    *(__half*)((char*)g_wh[arr] + off) = __float2half_rn(f);
}

// ---------------------------------------------------------------- fused GEMM
// 512 threads, 16 warps: warp grid 4(M) x 4(N), warp tile 32x64.
// Single fp16 GEMM: acc = x_fp16 * w_fp16 (fp32 accumulate).
// Selection exactness is restored downstream by refine_kernel.
template <int PHASE>
__global__ __launch_bounds__(512, 1)
void gemm_mlp_kernel(const float* __restrict__ obj, const float* __restrict__ geo,
                     const float* __restrict__ b1, const float* __restrict__ w2,
                     const float* __restrict__ b2, float* __restrict__ outv) {
    extern __shared__ char smraw[];
    char* sm = (char*)(((uintptr_t)smraw + 1023) & ~(uintptr_t)1023);
    __shared__ float s_b1[HH], s_w2[HH];
    __shared__ float red[128][5];
    __shared__ float rowlogit[128];

    const int t = threadIdx.x;
    const int wid = t >> 5, lane = t & 31;
    const int wm = wid >> 2;           // 0..3  (M warp)
    const int wn = wid & 3;            // 0..3  (N warp)
    const uint32_t smb = smem_u32(sm);

    if (t < HH) { s_b1[t] = b1[t]; s_w2[t] = w2[t]; }

    const char* wsrc = (const char*)g_wh[PHASE];

    const int rsub = t >> 4;          // 0..31
    const int f4   = t & 15;

    float acc[2][8][4];
#pragma unroll
    for (int a = 0; a < 2; a++)
#pragma unroll
        for (int b = 0; b < 8; b++)
#pragma unroll
            for (int cq = 0; cq < 4; cq++) acc[a][b][cq] = 0.f;

    uint2 xp[4];
    auto buildX = [&](int c) {
#pragma unroll
        for (int m = 0; m < 4; m++) {
            const int row = m * 32 + rsub;
            float4 x;
            if (PHASE == 0) {
                int pl = row >> 3, r = row & 7;
                int p = blockIdx.x * 16 + pl;
                int i = p >> 7, j = p & 127;
                const float4 a = *(const float4*)(obj + (size_t)(r * NN + i) * DD
                                                  + c * KC + f4 * 4);
                const float4 b = *(const float4*)(obj + (size_t)(r * NN + j) * DD
                                                  + c * KC + f4 * 4);
                const float4 g4 = *(const float4*)(geo
                    + (size_t)((r * NN + i) * NN + j) * DD + c * KC + f4 * 4);
                x.x = fmaf(a.x, b.x, g4.x);
                x.y = fmaf(a.y, b.y, g4.y);
                x.z = fmaf(a.z, b.z, g4.z);
                x.w = fmaf(a.w, b.w, g4.w);
            } else {
                int g = blockIdx.x * 128 + row;
                const float4 a = *(const float4*)(g_pf + (g >> 6) * DD
                                                  + c * KC + f4 * 4);
                const float4 b = *(const float4*)(g_pf + (g & 63) * DD
                                                  + c * KC + f4 * 4);
                x.x = a.x * b.x; x.y = a.y * b.y;
                x.z = a.z * b.z; x.w = a.w * b.w;
            }
            xp[m].x = pkh(x.x, x.y);
            xp[m].y = pkh(x.z, x.w);
        }
    };
    auto stageStore = [&](char* bs, uint32_t bsb, int c) {
#pragma unroll
        for (int m = 0; m < 4; m++) {
            const uint32_t boff = SWZ((uint32_t)((m * 32 + rsub) * 128 + f4 * 8));
            *(uint2*)(bs + OFF_A + boff) = xp[m];
        }
        const char* sW = wsrc + c * 32768;
#pragma unroll
        for (int m = 0; m < 4; m++) {
            uint32_t o = (uint32_t)(m * 8192 + t * 16);
            CP_ASYNC16(bsb + OFF_B + o, sW + o);
        }
        CP_COMMIT();
    };

    const uint32_t aRow = (uint32_t)(wm * 32 + (lane & 15));
    const uint32_t nRow = (uint32_t)(wn * 64 + (lane & 15));
    const uint32_t kbL  = (uint32_t)((lane >> 4) * 16);

    buildX(0);
    stageStore(sm, smb, 0);
    buildX(1);

#pragma unroll 1
    for (int c = 0; c < NCH; c++) {
        const int st = c & 1;
        const uint32_t sbb = smb + st * STG;
        if (c + 1 < NCH) {
            stageStore(sm + (st ^ 1) * STG, smb + (st ^ 1) * STG, c + 1);
            CP_WAIT1();
        } else {
            CP_WAIT0();
        }
        __syncthreads();
        const uint32_t sA = sbb + OFF_A;
        const uint32_t sB = sbb + OFF_B;
#pragma unroll
        for (int ks = 0; ks < 4; ks++) {
            const uint32_t kbase = ks * 32 + kbL;
            uint32_t ah[2][4];
#pragma unroll
            for (int mt = 0; mt < 2; mt++) {
                uint32_t off = SWZ((aRow + mt * 16) * 128 + kbase);
                ldsm4(ah[mt], sA + off);
            }
#pragma unroll
            for (int nh = 0; nh < 2; nh++) {
                uint32_t bh[2][4];
#pragma unroll
                for (int p = 0; p < 2; p++) {
                    uint32_t off = SWZ((nRow + nh * 32 + p * 16) * 128 + kbase);
                    ldsm4(bh[p], sB + off);
                }
#pragma unroll
                for (int mt = 0; mt < 2; mt++)
#pragma unroll
                    for (int p = 0; p < 2; p++)
#pragma unroll
                        for (int e = 0; e < 2; e++) {
                            float* d = acc[mt][nh * 4 + p * 2 + e];
                            mma16816(d, ah[mt], bh[p][e], bh[p][e + 2]);
                        }
            }
        }
        if (c + 2 < NCH) buildX(c + 2);
        __syncthreads();
    }

    // ---- epilogue: bias, relu, dot w2 ----
#pragma unroll
    for (int mt = 0; mt < 2; mt++) {
        float ps0 = 0.f, ps1 = 0.f;
#pragma unroll
        for (int nt = 0; nt < 8; nt++) {
            int h = wn * 64 + nt * 8 + (lane & 3) * 2;
            float b0 = s_b1[h],  w0 = s_w2[h];
            float b1v = s_b1[h + 1], w1v = s_w2[h + 1];
            ps0 = fmaf(fmaxf(acc[mt][nt][0] + b0, 0.f),  w0,  ps0);
            ps0 = fmaf(fmaxf(acc[mt][nt][1] + b1v, 0.f), w1v, ps0);
            ps1 = fmaf(fmaxf(acc[mt][nt][2] + b0, 0.f),  w0,  ps1);
            ps1 = fmaf(fmaxf(acc[mt][nt][3] + b1v, 0.f), w1v, ps1);
        }
        ps0 += __shfl_xor_sync(0xffffffffu, ps0, 1);
        ps0 += __shfl_xor_sync(0xffffffffu, ps0, 2);
        ps1 += __shfl_xor_sync(0xffffffffu, ps1, 1);
        ps1 += __shfl_xor_sync(0xffffffffu, ps1, 2);
        if ((lane & 3) == 0) {
            int r0 = wm * 32 + mt * 16 + (lane >> 2);
            red[r0][wn] = ps0;
            red[r0 + 8][wn] = ps1;
        }
    }
    __syncthreads();
    if (t < 128) rowlogit[t] = red[t][0] + red[t][1] + red[t][2] + red[t][3];
    __syncthreads();
    if (PHASE == 0) {
        if (t < 16) {
            float s = 0.f;
#pragma unroll
            for (int r = 0; r < 8; r++) s += rowlogit[t * 8 + r];
            outv[blockIdx.x * 16 + t] = s * 0.125f + b2[0];
        }
    } else {
        if (t < 128) outv[blockIdx.x * 128 + t] = rowlogit[t] + b2[0];
    }
}

// ---------------------------------------------------------------- threshold
// Bisect T so count(approx logit > T) lands in [96, 240]; compact to g_cand.
__global__ __launch_bounds__(1024) void thresh_kernel(const float* __restrict__ logits,
                                                      const float* __restrict__ mask) {
    const int t = threadIdx.x;
    const int wid = t >> 5, lane = t & 31;
    float v[16];
#pragma unroll
    for (int u = 0; u < 16; u++) {
        int p = u * 1024 + t;
        v[u] = (mask[p] != 0.f) ? logits[p] : -3.4e38f;
    }
    float mymax = -3.4e38f, mymin = 3.4e38f;
#pragma unroll
    for (int u = 0; u < 16; u++) {
        mymax = fmaxf(mymax, v[u]);
        if (v[u] > -1e38f) mymin = fminf(mymin, v[u]);
    }
    __shared__ float smax[32], smin[32];
    __shared__ int scnt[32];
    __shared__ float s_lo, s_hi;
#pragma unroll
    for (int o = 16; o > 0; o >>= 1) {
        mymax = fmaxf(mymax, __shfl_xor_sync(0xffffffffu, mymax, o));
        mymin = fminf(mymin, __shfl_xor_sync(0xffffffffu, mymin, o));
    }
    if (lane == 0) { smax[wid] = mymax; smin[wid] = mymin; }
    __syncthreads();
    if (t == 0) {
        float gx = smax[0], gn = smin[0];
        for (int w = 1; w < 32; w++) { gx = fmaxf(gx, smax[w]); gn = fminf(gn, smin[w]); }
        s_lo = gn - 1.0f;
        s_hi = gx;
    }
    __syncthreads();
    float lo = s_lo, hi = s_hi;

    __shared__ int s_c;
    for (int it = 0; it < 24; it++) {
        float mid = 0.5f * (lo + hi);
        int c = 0;
#pragma unroll
        for (int u = 0; u < 16; u++) c += (v[u] > mid);
        c = __reduce_add_sync(0xffffffffu, c);
        if (lane == 0) scnt[wid] = c;
        __syncthreads();
        if (wid == 0) {
            int cc = __reduce_add_sync(0xffffffffu, scnt[lane]);
            if (lane == 0) s_c = cc;
        }
        __syncthreads();
        int c_all = s_c;
        if (c_all >= 96 && c_all <= 240) { lo = mid; break; }
        if (c_all > 240) lo = mid; else hi = mid;
        __syncthreads();
    }
    __shared__ int s_cnt;
    __syncthreads();
    if (t == 0) s_cnt = 0;
    __syncthreads();
#pragma unroll
    for (int u = 0; u < 16; u++) {
        if (v[u] > lo) {
            int pos = atomicAdd(&s_cnt, 1);
            if (pos < NCAP) g_cand[pos] = u * 1024 + t;
        }
    }
    __syncthreads();
    if (t == 0) g_ncand = (s_cnt < NCAP) ? s_cnt : NCAP;
}

// ---------------------------------------------------------------- refine
// Exact fp32 r-mean logit per candidate. w1 streamed via cp.async
// double-buffered 32-d tiles; float4 xs reads; thread owns one h.
__global__ __launch_bounds__(256) void refine_kernel(const float* __restrict__ obj,
                                                     const float* __restrict__ geo,
                                                     const float* __restrict__ w1,
                                                     const float* __restrict__ b1,
                                                     const float* __restrict__ w2,
                                                     const float* __restrict__ b2) {
    extern __shared__ __align__(16) char rsm[];   // wt[2][32][HH] = 64 KB
    __shared__ int s_ind;
    __shared__ __align__(16) float xs[RR][DD];    // 16 KB
    __shared__ float rsum[8][RR];
    __shared__ float rtot[RR];
    const int ci = blockIdx.x;
    const int t = threadIdx.x;
    const int wid = t >> 5, lane = t & 31;
    const uint32_t wtb = smem_u32(rsm);
    if (t == 0) s_ind = (ci < g_ncand) ? g_cand[ci] : -1;
    __syncthreads();
    const int ind = s_ind;
    if (ind < 0) {
        if (t == 0) g_cand_logit[ci] = -3.4e38f;
        return;
    }
    const int i = ind >> 7, j = ind & 127;

    // prefetch w1 tile tt into buffer tt&1 (32 rows x 256 floats = 32 KB)
    auto pf = [&](int tt) {
        uint32_t dst = wtb + (uint32_t)(tt & 1) * 32768u;
        const char* src = (const char*)(w1 + (size_t)(tt * 32) * HH);
#pragma unroll
        for (int it = 0; it < 8; it++) {
            uint32_t o = (uint32_t)((it * 256 + t) * 16);
            CP_ASYNC16(dst + o, src + o);
        }
        CP_COMMIT();
    };
    pf(0);

    // build xs (vectorized, coalesced)
#pragma unroll
    for (int rr = 0; rr < 4; rr++) {
        int r = rr * 2 + (t >> 7);
        int d4 = (t & 127) * 4;
        const float4 oi = *(const float4*)&obj[(size_t)(r * NN + i) * DD + d4];
        const float4 oj = *(const float4*)&obj[(size_t)(r * NN + j) * DD + d4];
        const float4 g4 = *(const float4*)&geo[(size_t)((r * NN + i) * NN + j) * DD + d4];
        float4 xv;
        xv.x = fmaf(oi.x, oj.x, g4.x);
        xv.y = fmaf(oi.y, oj.y, g4.y);
        xv.z = fmaf(oi.z, oj.z, g4.z);
        xv.w = fmaf(oi.w, oj.w, g4.w);
        *(float4*)&xs[r][d4] = xv;
    }

    float z[RR];
#pragma unroll
    for (int r = 0; r < RR; r++) z[r] = 0.f;
    const int h = t;
#pragma unroll 1
    for (int tt = 0; tt < 16; tt++) {
        if (tt + 1 < 16) { pf(tt + 1); CP_WAIT1(); } else { CP_WAIT0(); }
        __syncthreads();                       // tile tt visible; xs built
        const float* wt = (const float*)(rsm + (tt & 1) * 32768);
        const int d0 = tt * 32;
#pragma unroll
        for (int q4 = 0; q4 < 8; q4++) {
            float w0 = wt[(q4 * 4 + 0) * HH + h];
            float w1v = wt[(q4 * 4 + 1) * HH + h];
            float w2v = wt[(q4 * 4 + 2) * HH + h];
            float w3 = wt[(q4 * 4 + 3) * HH + h];
#pragma unroll
            for (int r = 0; r < RR; r++) {
                const float4 xv = *(const float4*)&xs[r][d0 + q4 * 4];
                z[r] = fmaf(xv.x, w0, z[r]);
                z[r] = fmaf(xv.y, w1v, z[r]);
                z[r] = fmaf(xv.z, w2v, z[r]);
                z[r] = fmaf(xv.w, w3, z[r]);
            }
        }
        __syncthreads();                       // done reading buffer tt&1
    }
    const float bb = b1[h], ww = w2[h];
#pragma unroll
    for (int r = 0; r < RR; r++) {
        float v = fmaxf(z[r] + bb, 0.f) * ww;
#pragma unroll
        for (int o = 16; o > 0; o >>= 1) v += __shfl_xor_sync(0xffffffffu, v, o);
        if (lane == 0) rsum[wid][r] = v;
    }
    __syncthreads();
    if (t < RR) {
        float s = 0.f;
#pragma unroll
        for (int w = 0; w < 8; w++) s += rsum[w][t];
        rtot[t] = s;
    }
    __syncthreads();
    if (t == 0) {
        float s = 0.f;
#pragma unroll
        for (int r = 0; r < RR; r++) s += rtot[r];
        g_cand_logit[ci] = s * 0.125f + b2[0];
    }
}

// ---------------------------------------------------------------- final top-64
__global__ __launch_bounds__(32) void final_topk_kernel(float* __restrict__ out_inds) {
    const int lane = threadIdx.x;
    float v[8];
    int idx[8];
#pragma unroll
    for (int u = 0; u < 8; u++) {
        v[u] = g_cand_logit[lane * 8 + u];
        idx[u] = (v[u] > -1e38f) ? g_cand[lane * 8 + u] : (1 << 30);
    }
    float lmax = -3.4e38f; int li = 1 << 30, ls = 0;
#pragma unroll
    for (int u = 0; u < 8; u++)
        if (v[u] > lmax || (v[u] == lmax && idx[u] < li)) { lmax = v[u]; li = idx[u]; ls = u; }

    for (int sel = 0; sel < KTOP; sel++) {
        float bv = lmax; int bi = li;
#pragma unroll
        for (int o = 16; o > 0; o >>= 1) {
            float ov = __shfl_xor_sync(0xffffffffu, bv, o);
            int oi = __shfl_xor_sync(0xffffffffu, bi, o);
            if (ov > bv || (ov == bv && oi < bi)) { bv = ov; bi = oi; }
        }
        if (lane == 0) { g_topk[sel] = bi; out_inds[sel] = (float)bi; }
        if (bi == li) {
            v[ls] = -3.4e38f; idx[ls] = 1 << 30;
            lmax = -3.4e38f; li = 1 << 30; ls = 0;
#pragma unroll
            for (int u = 0; u < 8; u++)
                if (v[u] > lmax || (v[u] == lmax && idx[u] < li)) { lmax = v[u]; li = idx[u]; ls = u; }
        }
    }
}

// ---------------------------------------------------------------- gather
__global__ void gather_pf_kernel(const float* __restrict__ obj,
                                 const float* __restrict__ geo) {
    const int b = blockIdx.x;
    const int ind = g_topk[b];
    const int i = ind >> 7, j = ind & 127;
    const int d = threadIdx.x * 4;
    float4 a = make_float4(0.f, 0.f, 0.f, 0.f);
#pragma unroll
    for (int r = 0; r < RR; r++) {
        const float4 oi = *(const float4*)&obj[(size_t)(r * NN + i) * DD + d];
        const float4 oj = *(const float4*)&obj[(size_t)(r * NN + j) * DD + d];
        const float4 g4 = *(const float4*)&geo[(size_t)((r * NN + i) * NN + j) * DD + d];
        a.x += fmaf(oi.x, oj.x, g4.x);
        a.y += fmaf(oi.y, oj.y, g4.y);
        a.z += fmaf(oi.z, oj.z, g4.z);
        a.w += fmaf(oi.w, oj.w, g4.w);
    }
    a.x *= (1.f / RR); a.y *= (1.f / RR); a.z *= (1.f / RR); a.w *= (1.f / RR);
    *(float4*)&g_pf[b * DD + d] = a;
}

// ---------------------------------------------------------------- launch
extern "C" void kernel_launch(void* const* d_in, const int* in_sizes, int n_in,
                              void* d_out, int out_size) {
    const float* obj  = (const float*)d_in[0];
    const float* geo  = (const float*)d_in[1];
    const float* mask = (const float*)d_in[2];
    const float* w1a  = (const float*)d_in[3];
    const float* b1a  = (const float*)d_in[4];
    const float* w2a  = (const float*)d_in[5];
    const float* b2a  = (const float*)d_in[6];
    const float* w1b  = (const float*)d_in[7];
    const float* b1b  = (const float*)d_in[8];
    const float* w2b  = (const float*)d_in[9];
    const float* b2b  = (const float*)d_in[10];
    float* out = (float*)d_out;

    const int dyn = 2 * STG + 1024;  // +1024 for manual alignment
    cudaFuncSetAttribute(gemm_mlp_kernel<0>,
                         cudaFuncAttributeMaxDynamicSharedMemorySize, dyn);
    cudaFuncSetAttribute(gemm_mlp_kernel<1>,
                         cudaFuncAttributeMaxDynamicSharedMemorySize, dyn);
    cudaFuncSetAttribute(refine_kernel,
                         cudaFuncAttributeMaxDynamicSharedMemorySize, 65536);

    prep_w_kernel<<<1024, 256>>>(w1a, w1b);
    gemm_mlp_kernel<0><<<NPAIR / 16, 512, dyn>>>(obj, geo, b1a, w2a, b2a, out);
    thresh_kernel<<<1, 1024>>>(out, mask);
    refine_kernel<<<NCAP, 256, 65536>>>(obj, geo, w1a, b1a, w2a, b2a);
    final_topk_kernel<<<1, 32>>>(out + NPAIR + KTOP * KTOP);
    gather_pf_kernel<<<KTOP, 128>>>(obj, geo);
    gemm_mlp_kernel<1><<<KTOP * KTOP / 128, 512, dyn>>>(obj, geo, b1b, w2b, b2b,
                                                        out + NPAIR);
}

// round 16
// speedup vs baseline: 2.6328x; 1.0187x over previous
#include <cuda_runtime.h>
#include <cuda_fp16.h>
#include <cstdint>
#include <math.h>

// ---------------------------------------------------------------- constants
#define RR 8
#define NN 128
#define DD 512
#define HH 256
#define KTOP 64
#define NCAP 160               // candidate capacity
#define NPAIR (NN*NN)          // 16384
#define KC 64                  // K per chunk (64 fp16 = 128B rows, SW128 atom)
#define NCH 8                  // 512 / 64
#define STG 49152              // bytes per smem stage (A + B)
#define OFF_A 0                // 16384 B  (128 rows x 128B)
#define OFF_B 16384            // 32768 B  (256 rows x 128B)
#define SWZ(o) ((o) ^ (((o) >> 3) & 0x70))

// ---------------------------------------------------------------- scratch
__device__ float g_pf[KTOP * DD];                 // topk mean pair feats
__device__ float g_pf_cand[NCAP * DD];            // per-candidate mean feats
__device__ int   g_topk_ci[KTOP];                 // winning candidate slot
__device__ int   g_cand[NCAP];
__device__ float g_cand_logit[NCAP];
__device__ int   g_ncand;
__device__ __align__(16) __half g_wh[2][NCH * 16384];  // W fp16, swizzled

// ---------------------------------------------------------------- helpers
static __device__ __forceinline__ uint32_t smem_u32(const void* p) {
    uint32_t a;
    asm("{ .reg .u64 t; cvta.to.shared.u64 t, %1; cvt.u32.u64 %0, t; }"
        : "=r"(a) : "l"(p));
    return a;
}
static __device__ __forceinline__ void ldsm4(uint32_t* r, uint32_t addr) {
    asm volatile("ldmatrix.sync.aligned.m8n8.x4.shared.b16 {%0,%1,%2,%3}, [%4];"
                 : "=r"(r[0]), "=r"(r[1]), "=r"(r[2]), "=r"(r[3]) : "r"(addr));
}
static __device__ __forceinline__ void mma16816(float* d, const uint32_t* a,
                                                uint32_t b0, uint32_t b1) {
    asm volatile(
        "mma.sync.aligned.m16n8k16.row.col.f32.f16.f16.f32 "
        "{%0,%1,%2,%3}, {%4,%5,%6,%7}, {%8,%9}, {%0,%1,%2,%3};"
        : "+f"(d[0]), "+f"(d[1]), "+f"(d[2]), "+f"(d[3])
        : "r"(a[0]), "r"(a[1]), "r"(a[2]), "r"(a[3]), "r"(b0), "r"(b1));
}
#define CP_ASYNC16(dst, src) \
    asm volatile("cp.async.cg.shared.global [%0], [%1], 16;" \
                 :: "r"(dst), "l"(src) : "memory")
#define CP_COMMIT() asm volatile("cp.async.commit_group;" ::: "memory")
#define CP_WAIT0()  asm volatile("cp.async.wait_group 0;" ::: "memory")
#define CP_WAIT1()  asm volatile("cp.async.wait_group 1;" ::: "memory")

static __device__ __forceinline__ uint32_t pkh(float a, float b) {
    __half2 h2 = __floats2half2_rn(a, b);
    return *reinterpret_cast<uint32_t*>(&h2);
}

// ---------------------------------------------------------------- W prep
// W1 (fp32 [512,256]) -> fp16, transposed to [n][k] per K-chunk, swizzled.
__global__ void prep_w_kernel(const float* __restrict__ w1a,
                              const float* __restrict__ w1b) {
    int idx = blockIdx.x * 256 + threadIdx.x;      // 0..262143
    int arr = idx >> 17;
    int rem = idx & 131071;
    int c  = rem >> 14;
    int n  = (rem >> 6) & 255;
    int kk = rem & 63;
    const float* w = arr ? w1b : w1a;
    float f = w[(size_t)(c * 64 + kk) * HH + n];
    uint32_t off = (uint32_t)c * 32768u + SWZ((uint32_t)(n * 128 + kk * 2));
    *(__half*)((char*)g_wh[arr] + off) = __float2half_rn(f);
}

// ---------------------------------------------------------------- fused GEMM
// 512 threads, 16 warps: warp grid 4(M) x 4(N), warp tile 32x64.
// Single fp16 GEMM: acc = x_fp16 * w_fp16 (fp32 accumulate).
// Selection exactness is restored downstream by refine_kernel.
template <int PHASE>
__global__ __launch_bounds__(512, 1)
void gemm_mlp_kernel(const float* __restrict__ obj, const float* __restrict__ geo,
                     const float* __restrict__ b1, const float* __restrict__ w2,
                     const float* __restrict__ b2, float* __restrict__ outv) {
    extern __shared__ char smraw[];
    char* sm = (char*)(((uintptr_t)smraw + 1023) & ~(uintptr_t)1023);
    __shared__ float s_b1[HH], s_w2[HH];
    __shared__ float red[128][5];
    __shared__ float rowlogit[128];

    const int t = threadIdx.x;
    const int wid = t >> 5, lane = t & 31;
    const int wm = wid >> 2;           // 0..3  (M warp)
    const int wn = wid & 3;            // 0..3  (N warp)
    const uint32_t smb = smem_u32(sm);

    if (t < HH) { s_b1[t] = b1[t]; s_w2[t] = w2[t]; }

    const char* wsrc = (const char*)g_wh[PHASE];

    const int rsub = t >> 4;          // 0..31
    const int f4   = t & 15;

    float acc[2][8][4];
#pragma unroll
    for (int a = 0; a < 2; a++)
#pragma unroll
        for (int b = 0; b < 8; b++)
#pragma unroll
            for (int cq = 0; cq < 4; cq++) acc[a][b][cq] = 0.f;

    uint2 xp[4];
    auto buildX = [&](int c) {
#pragma unroll
        for (int m = 0; m < 4; m++) {
            const int row = m * 32 + rsub;
            float4 x;
            if (PHASE == 0) {
                int pl = row >> 3, r = row & 7;
                int p = blockIdx.x * 16 + pl;
                int i = p >> 7, j = p & 127;
                const float4 a = *(const float4*)(obj + (size_t)(r * NN + i) * DD
                                                  + c * KC + f4 * 4);
                const float4 b = *(const float4*)(obj + (size_t)(r * NN + j) * DD
                                                  + c * KC + f4 * 4);
                const float4 g4 = *(const float4*)(geo
                    + (size_t)((r * NN + i) * NN + j) * DD + c * KC + f4 * 4);
                x.x = fmaf(a.x, b.x, g4.x);
                x.y = fmaf(a.y, b.y, g4.y);
                x.z = fmaf(a.z, b.z, g4.z);
                x.w = fmaf(a.w, b.w, g4.w);
            } else {
                int g = blockIdx.x * 128 + row;
                const float4 a = *(const float4*)(g_pf + (g >> 6) * DD
                                                  + c * KC + f4 * 4);
                const float4 b = *(const float4*)(g_pf + (g & 63) * DD
                                                  + c * KC + f4 * 4);
                x.x = a.x * b.x; x.y = a.y * b.y;
                x.z = a.z * b.z; x.w = a.w * b.w;
            }
            xp[m].x = pkh(x.x, x.y);
            xp[m].y = pkh(x.z, x.w);
        }
    };
    auto stageStore = [&](char* bs, uint32_t bsb, int c) {
#pragma unroll
        for (int m = 0; m < 4; m++) {
            const uint32_t boff = SWZ((uint32_t)((m * 32 + rsub) * 128 + f4 * 8));
            *(uint2*)(bs + OFF_A + boff) = xp[m];
        }
        const char* sW = wsrc + c * 32768;
#pragma unroll
        for (int m = 0; m < 4; m++) {
            uint32_t o = (uint32_t)(m * 8192 + t * 16);
            CP_ASYNC16(bsb + OFF_B + o, sW + o);
        }
        CP_COMMIT();
    };

    const uint32_t aRow = (uint32_t)(wm * 32 + (lane & 15));
    const uint32_t nRow = (uint32_t)(wn * 64 + (lane & 15));
    const uint32_t kbL  = (uint32_t)((lane >> 4) * 16);

    buildX(0);
    stageStore(sm, smb, 0);
    buildX(1);

#pragma unroll 1
    for (int c = 0; c < NCH; c++) {
        const int st = c & 1;
        const uint32_t sbb = smb + st * STG;
        if (c + 1 < NCH) {
            stageStore(sm + (st ^ 1) * STG, smb + (st ^ 1) * STG, c + 1);
            CP_WAIT1();
        } else {
            CP_WAIT0();
        }
        __syncthreads();
        const uint32_t sA = sbb + OFF_A;
        const uint32_t sB = sbb + OFF_B;
#pragma unroll
        for (int ks = 0; ks < 4; ks++) {
            const uint32_t kbase = ks * 32 + kbL;
            uint32_t ah[2][4];
#pragma unroll
            for (int mt = 0; mt < 2; mt++) {
                uint32_t off = SWZ((aRow + mt * 16) * 128 + kbase);
                ldsm4(ah[mt], sA + off);
            }
#pragma unroll
            for (int nh = 0; nh < 2; nh++) {
                uint32_t bh[2][4];
#pragma unroll
                for (int p = 0; p < 2; p++) {
                    uint32_t off = SWZ((nRow + nh * 32 + p * 16) * 128 + kbase);
                    ldsm4(bh[p], sB + off);
                }
#pragma unroll
                for (int mt = 0; mt < 2; mt++)
#pragma unroll
                    for (int p = 0; p < 2; p++)
#pragma unroll
                        for (int e = 0; e < 2; e++) {
                            float* d = acc[mt][nh * 4 + p * 2 + e];
                            mma16816(d, ah[mt], bh[p][e], bh[p][e + 2]);
                        }
            }
        }
        if (c + 2 < NCH) buildX(c + 2);
        __syncthreads();
    }

    // ---- epilogue: bias, relu, dot w2 ----
#pragma unroll
    for (int mt = 0; mt < 2; mt++) {
        float ps0 = 0.f, ps1 = 0.f;
#pragma unroll
        for (int nt = 0; nt < 8; nt++) {
            int h = wn * 64 + nt * 8 + (lane & 3) * 2;
            float b0 = s_b1[h],  w0 = s_w2[h];
            float b1v = s_b1[h + 1], w1v = s_w2[h + 1];
            ps0 = fmaf(fmaxf(acc[mt][nt][0] + b0, 0.f),  w0,  ps0);
            ps0 = fmaf(fmaxf(acc[mt][nt][1] + b1v, 0.f), w1v, ps0);
            ps1 = fmaf(fmaxf(acc[mt][nt][2] + b0, 0.f),  w0,  ps1);
            ps1 = fmaf(fmaxf(acc[mt][nt][3] + b1v, 0.f), w1v, ps1);
        }
        ps0 += __shfl_xor_sync(0xffffffffu, ps0, 1);
        ps0 += __shfl_xor_sync(0xffffffffu, ps0, 2);
        ps1 += __shfl_xor_sync(0xffffffffu, ps1, 1);
        ps1 += __shfl_xor_sync(0xffffffffu, ps1, 2);
        if ((lane & 3) == 0) {
            int r0 = wm * 32 + mt * 16 + (lane >> 2);
            red[r0][wn] = ps0;
            red[r0 + 8][wn] = ps1;
        }
    }
    __syncthreads();
    if (t < 128) rowlogit[t] = red[t][0] + red[t][1] + red[t][2] + red[t][3];
    __syncthreads();
    if (PHASE == 0) {
        if (t < 16) {
            float s = 0.f;
#pragma unroll
            for (int r = 0; r < 8; r++) s += rowlogit[t * 8 + r];
            outv[blockIdx.x * 16 + t] = s * 0.125f + b2[0];
        }
    } else {
        if (t < 128) outv[blockIdx.x * 128 + t] = rowlogit[t] + b2[0];
    }
}

// ---------------------------------------------------------------- threshold
// Bisect T so count(approx logit > T) lands in [80, 150]; compact to g_cand.
__global__ __launch_bounds__(1024) void thresh_kernel(const float* __restrict__ logits,
                                                      const float* __restrict__ mask) {
    const int t = threadIdx.x;
    const int wid = t >> 5, lane = t & 31;
    float v[16];
#pragma unroll
    for (int u = 0; u < 16; u++) {
        int p = u * 1024 + t;
        v[u] = (mask[p] != 0.f) ? logits[p] : -3.4e38f;
    }
    float mymax = -3.4e38f, mymin = 3.4e38f;
#pragma unroll
    for (int u = 0; u < 16; u++) {
        mymax = fmaxf(mymax, v[u]);
        if (v[u] > -1e38f) mymin = fminf(mymin, v[u]);
    }
    __shared__ float smax[32], smin[32];
    __shared__ int scnt[32];
    __shared__ float s_lo, s_hi;
#pragma unroll
    for (int o = 16; o > 0; o >>= 1) {
        mymax = fmaxf(mymax, __shfl_xor_sync(0xffffffffu, mymax, o));
        mymin = fminf(mymin, __shfl_xor_sync(0xffffffffu, mymin, o));
    }
    if (lane == 0) { smax[wid] = mymax; smin[wid] = mymin; }
    __syncthreads();
    if (t == 0) {
        float gx = smax[0], gn = smin[0];
        for (int w = 1; w < 32; w++) { gx = fmaxf(gx, smax[w]); gn = fminf(gn, smin[w]); }
        s_lo = gn - 1.0f;
        s_hi = gx;
    }
    __syncthreads();
    float lo = s_lo, hi = s_hi;

    __shared__ int s_c;
    for (int it = 0; it < 32; it++) {
        float mid = 0.5f * (lo + hi);
        int c = 0;
#pragma unroll
        for (int u = 0; u < 16; u++) c += (v[u] > mid);
        c = __reduce_add_sync(0xffffffffu, c);
        if (lane == 0) scnt[wid] = c;
        __syncthreads();
        if (wid == 0) {
            int cc = __reduce_add_sync(0xffffffffu, scnt[lane]);
            if (lane == 0) s_c = cc;
        }
        __syncthreads();
        int c_all = s_c;
        if (c_all >= 80 && c_all <= 150) { lo = mid; break; }
        if (c_all > 150) lo = mid; else hi = mid;
        __syncthreads();
    }
    __shared__ int s_cnt;
    __syncthreads();
    if (t == 0) s_cnt = 0;
    __syncthreads();
#pragma unroll
    for (int u = 0; u < 16; u++) {
        if (v[u] > lo) {
            int pos = atomicAdd(&s_cnt, 1);
            if (pos < NCAP) g_cand[pos] = u * 1024 + t;
        }
    }
    __syncthreads();
    if (t == 0) g_ncand = (s_cnt < NCAP) ? s_cnt : NCAP;
}

// ---------------------------------------------------------------- refine
// Exact fp32 r-mean logit per candidate + exact mean pair features.
// 512 threads: (rh = t>>8) x (h = t&255); w1 cp.async double-buffered tiles.
__global__ __launch_bounds__(512) void refine_kernel(const float* __restrict__ obj,
                                                     const float* __restrict__ geo,
                                                     const float* __restrict__ w1,
                                                     const float* __restrict__ b1,
                                                     const float* __restrict__ w2,
                                                     const float* __restrict__ b2) {
    extern __shared__ __align__(16) char rsm[];   // wt[2][32][HH] = 64 KB
    __shared__ int s_ind;
    __shared__ __align__(16) float xs[RR][DD];    // 16 KB
    __shared__ float wsum[16];
    const int ci = blockIdx.x;
    const int t = threadIdx.x;
    const int wid = t >> 5, lane = t & 31;
    const int rh = t >> 8;            // 0..1 (r half)
    const int h  = t & 255;
    const uint32_t wtb = smem_u32(rsm);
    if (t == 0) s_ind = (ci < g_ncand) ? g_cand[ci] : -1;
    __syncthreads();
    const int ind = s_ind;
    if (ind < 0) {
        if (t == 0) g_cand_logit[ci] = -3.4e38f;
        return;
    }
    const int i = ind >> 7, j = ind & 127;

    // prefetch w1 tile tt into buffer tt&1 (32 rows x 256 floats = 32 KB)
    auto pf = [&](int tt) {
        uint32_t dst = wtb + (uint32_t)(tt & 1) * 32768u;
        const char* src = (const char*)(w1 + (size_t)(tt * 32) * HH);
#pragma unroll
        for (int it = 0; it < 4; it++) {
            uint32_t o = (uint32_t)((it * 512 + t) * 16);
            CP_ASYNC16(dst + o, src + o);
        }
        CP_COMMIT();
    };
    pf(0);

    // build xs (vectorized, coalesced): 2 float4 per thread
#pragma unroll
    for (int q = 0; q < 2; q++) {
        int f4id = t * 2 + q;           // 0..1023
        int r = f4id >> 7;
        int d4 = (f4id & 127) * 4;
        const float4 oi = *(const float4*)&obj[(size_t)(r * NN + i) * DD + d4];
        const float4 oj = *(const float4*)&obj[(size_t)(r * NN + j) * DD + d4];
        const float4 g4 = *(const float4*)&geo[(size_t)((r * NN + i) * NN + j) * DD + d4];
        float4 xv;
        xv.x = fmaf(oi.x, oj.x, g4.x);
        xv.y = fmaf(oi.y, oj.y, g4.y);
        xv.z = fmaf(oi.z, oj.z, g4.z);
        xv.w = fmaf(oi.w, oj.w, g4.w);
        *(float4*)&xs[r][d4] = xv;
    }
    __syncthreads();
    // exact mean pair features for this candidate (d = t)
    {
        float s = 0.f;
#pragma unroll
        for (int r = 0; r < RR; r++) s += xs[r][t];
        g_pf_cand[(size_t)ci * DD + t] = s * 0.125f;
    }

    float z[4];
#pragma unroll
    for (int r = 0; r < 4; r++) z[r] = 0.f;
#pragma unroll 1
    for (int tt = 0; tt < 16; tt++) {
        if (tt + 1 < 16) { pf(tt + 1); CP_WAIT1(); } else { CP_WAIT0(); }
        __syncthreads();                       // tile tt visible
        const float* wt = (const float*)(rsm + (tt & 1) * 32768);
        const int d0 = tt * 32;
#pragma unroll
        for (int q4 = 0; q4 < 8; q4++) {
            float w0 = wt[(q4 * 4 + 0) * HH + h];
            float w1v = wt[(q4 * 4 + 1) * HH + h];
            float w2v = wt[(q4 * 4 + 2) * HH + h];
            float w3 = wt[(q4 * 4 + 3) * HH + h];
#pragma unroll
            for (int r = 0; r < 4; r++) {
                const float4 xv = *(const float4*)&xs[rh * 4 + r][d0 + q4 * 4];
                z[r] = fmaf(xv.x, w0, z[r]);
                z[r] = fmaf(xv.y, w1v, z[r]);
                z[r] = fmaf(xv.z, w2v, z[r]);
                z[r] = fmaf(xv.w, w3, z[r]);
            }
        }
        __syncthreads();                       // done reading buffer tt&1
    }
    const float bb = b1[h], ww = w2[h];
    float part = 0.f;
#pragma unroll
    for (int r = 0; r < 4; r++) part = fmaf(fmaxf(z[r] + bb, 0.f), ww, part);
#pragma unroll
    for (int o = 16; o > 0; o >>= 1) part += __shfl_xor_sync(0xffffffffu, part, o);
    if (lane == 0) wsum[wid] = part;
    __syncthreads();
    if (t == 0) {
        float s = 0.f;
#pragma unroll
        for (int w = 0; w < 16; w++) s += wsum[w];
        g_cand_logit[ci] = s * 0.125f + b2[0];
    }
}

// ---------------------------------------------------------------- final top-64
// Single warp; 160 (value, pair-idx, slot) register-resident.
__global__ __launch_bounds__(32) void final_topk_kernel(float* __restrict__ out_inds) {
    const int lane = threadIdx.x;
    float v[5];
    int idx[5];
#pragma unroll
    for (int u = 0; u < 5; u++) {
        int slot = lane * 5 + u;
        v[u] = g_cand_logit[slot];
        idx[u] = (v[u] > -1e38f) ? g_cand[slot] : (1 << 30);
    }
    float lmax = -3.4e38f; int li = 1 << 30, ls = 0;
#pragma unroll
    for (int u = 0; u < 5; u++)
        if (v[u] > lmax || (v[u] == lmax && idx[u] < li)) { lmax = v[u]; li = idx[u]; ls = u; }

    for (int sel = 0; sel < KTOP; sel++) {
        float bv = lmax; int bi = li; int bc = lane * 5 + ls;
#pragma unroll
        for (int o = 16; o > 0; o >>= 1) {
            float ov = __shfl_xor_sync(0xffffffffu, bv, o);
            int oi = __shfl_xor_sync(0xffffffffu, bi, o);
            int oc = __shfl_xor_sync(0xffffffffu, bc, o);
            if (ov > bv || (ov == bv && oi < bi)) { bv = ov; bi = oi; bc = oc; }
        }
        if (lane == 0) { g_topk_ci[sel] = bc; out_inds[sel] = (float)bi; }
        if (bi == li) {                    // this lane owned the winner
            v[ls] = -3.4e38f; idx[ls] = 1 << 30;
            lmax = -3.4e38f; li = 1 << 30; ls = 0;
#pragma unroll
            for (int u = 0; u < 5; u++)
                if (v[u] > lmax || (v[u] == lmax && idx[u] < li)) { lmax = v[u]; li = idx[u]; ls = u; }
        }
    }
}

// ---------------------------------------------------------------- pf remap
// g_pf[sel] = g_pf_cand[topk_ci[sel]]  (64 x 512 float copy)
__global__ void remap_pf_kernel() {
    const int b = blockIdx.x;
    const int ci = g_topk_ci[b];
    const int d = threadIdx.x * 4;
    *(float4*)&g_pf[(size_t)b * DD + d] =
        *(const float4*)&g_pf_cand[(size_t)ci * DD + d];
}

// ---------------------------------------------------------------- launch
extern "C" void kernel_launch(void* const* d_in, const int* in_sizes, int n_in,
                              void* d_out, int out_size) {
    const float* obj  = (const float*)d_in[0];
    const float* geo  = (const float*)d_in[1];
    const float* mask = (const float*)d_in[2];
    const float* w1a  = (const float*)d_in[3];
    const float* b1a  = (const float*)d_in[4];
    const float* w2a  = (const float*)d_in[5];
    const float* b2a  = (const float*)d_in[6];
    const float* w1b  = (const float*)d_in[7];
    const float* b1b  = (const float*)d_in[8];
    const float* w2b  = (const float*)d_in[9];
    const float* b2b  = (const float*)d_in[10];
    float* out = (float*)d_out;

    const int dyn = 2 * STG + 1024;  // +1024 for manual alignment
    cudaFuncSetAttribute(gemm_mlp_kernel<0>,
                         cudaFuncAttributeMaxDynamicSharedMemorySize, dyn);
    cudaFuncSetAttribute(gemm_mlp_kernel<1>,
                         cudaFuncAttributeMaxDynamicSharedMemorySize, dyn);
    cudaFuncSetAttribute(refine_kernel,
                         cudaFuncAttributeMaxDynamicSharedMemorySize, 65536);

    prep_w_kernel<<<1024, 256>>>(w1a, w1b);
    gemm_mlp_kernel<0><<<NPAIR / 16, 512, dyn>>>(obj, geo, b1a, w2a, b2a, out);
    thresh_kernel<<<1, 1024>>>(out, mask);
    refine_kernel<<<NCAP, 512, 65536>>>(obj, geo, w1a, b1a, w2a, b2a);
    final_topk_kernel<<<1, 32>>>(out + NPAIR + KTOP * KTOP);
    remap_pf_kernel<<<KTOP, 128>>>();
    gemm_mlp_kernel<1><<<KTOP * KTOP / 128, 512, dyn>>>(obj, geo, b1b, w2b, b2b,
                                                        out + NPAIR);
}